// round 2
// baseline (speedup 1.0000x reference)
#include <cuda_runtime.h>
#include <math.h>

// Problem constants (fixed by reference: N=50000, E=800000, C=96, H=4, CH=24)
#define NMAX 50000
#define EMAX 800000
#define C 96
#define NH 4
#define CH 24
#define NEG_SLOPE 0.2f
#define LN_EPS 1e-5f

// ---------------- device scratch (static, no allocation) ----------------
__device__ float g_h[NMAX * C];        // 19.2 MB
__device__ float g_asrc[NMAX * NH];
__device__ float g_adst[NMAX * NH];
__device__ int   g_deg[NMAX];
__device__ int   g_rowptr[NMAX + 1];
__device__ int   g_widx[NMAX];
__device__ int   g_csr[EMAX];

#define SCAN_TILE 1024
#define NBLK_SCAN ((NMAX + SCAN_TILE - 1) / SCAN_TILE)   // 49
__device__ int g_bsum[NBLK_SCAN];
__device__ int g_bsumx[NBLK_SCAN];

// ---------------- zero degree counters ----------------
__global__ void kzero(int n) {
    int i = blockIdx.x * blockDim.x + threadIdx.x;
    if (i < n) g_deg[i] = 0;
}

// ---------------- GEMM: h = x @ W  (fp32, smem tiled) ----------------
// block: 96 threads, 24 rows per block. smem: 36.9KB (W) + 9.6KB (x) < 48KB.
// micro-tile per thread: 6 rows x 4 cols.
#define BR 24
__global__ void __launch_bounds__(96) kgemm(const float* __restrict__ x,
                                            const float* __restrict__ W, int n) {
    __shared__ __align__(16) float Ws[96 * 96];   // 36864 B
    __shared__ float xs[BR][100];                 // 9600 B; stride 100 avoids conflicts
    int t = threadIdx.x;
    for (int idx = t; idx < 96 * 96; idx += 96) Ws[idx] = W[idx];
    int r0 = blockIdx.x * BR;
    int rows = min(BR, n - r0);
    for (int idx = t; idx < rows * 96; idx += 96) {
        int r = idx / 96;           // c == t (coalesced)
        xs[r][t] = x[(r0 + r) * 96 + t];
    }
    __syncthreads();

    int tc = t % 24;   // col group: cols tc*4 .. tc*4+3
    int tr = t / 24;   // row group: rows tr*6 .. tr*6+5
    float acc[6][4];
#pragma unroll
    for (int p = 0; p < 6; p++)
#pragma unroll
        for (int q = 0; q < 4; q++) acc[p][q] = 0.f;

#pragma unroll 4
    for (int k = 0; k < 96; k++) {
        float4 wv = *(const float4*)&Ws[k * 96 + tc * 4];
        float xv[6];
#pragma unroll
        for (int p = 0; p < 6; p++) xv[p] = xs[tr * 6 + p][k];
#pragma unroll
        for (int p = 0; p < 6; p++) {
            acc[p][0] += xv[p] * wv.x;
            acc[p][1] += xv[p] * wv.y;
            acc[p][2] += xv[p] * wv.z;
            acc[p][3] += xv[p] * wv.w;
        }
    }
#pragma unroll
    for (int p = 0; p < 6; p++) {
        int gr = r0 + tr * 6 + p;
        if (gr < n) {
            float4 st = make_float4(acc[p][0], acc[p][1], acc[p][2], acc[p][3]);
            *(float4*)&g_h[gr * 96 + tc * 4] = st;
        }
    }
}

// ---------------- per-node attention coefficients ----------------
// one warp per node; lanes 0..23 cover channels of each head.
__global__ void kattn(const float* __restrict__ att_src,
                      const float* __restrict__ att_dst, int n) {
    int gw = (blockIdx.x * blockDim.x + threadIdx.x) >> 5;
    int lane = threadIdx.x & 31;
    if (gw >= n) return;
#pragma unroll
    for (int hh = 0; hh < NH; hh++) {
        float v  = (lane < CH) ? g_h[gw * C + hh * CH + lane] : 0.f;
        float ps = (lane < CH) ? v * att_src[hh * CH + lane] : 0.f;
        float pd = (lane < CH) ? v * att_dst[hh * CH + lane] : 0.f;
#pragma unroll
        for (int off = 16; off > 0; off >>= 1) {
            ps += __shfl_down_sync(0xffffffffu, ps, off);
            pd += __shfl_down_sync(0xffffffffu, pd, off);
        }
        if (lane == 0) {
            g_asrc[gw * NH + hh] = ps;
            g_adst[gw * NH + hh] = pd;
        }
    }
}

// ---------------- CSR build ----------------
__global__ void khist(const int* __restrict__ ei, int e) {
    int i = blockIdx.x * blockDim.x + threadIdx.x;
    if (i < e) atomicAdd(&g_deg[ei[e + i]], 1);   // dst = ei[1][i]
}

__global__ void kscan1(int n) {
    int b = blockIdx.x, t = threadIdx.x;
    int base = b * SCAN_TILE + t * 4;
    int v[4];
    int local = 0;
#pragma unroll
    for (int q = 0; q < 4; q++) {
        v[q] = (base + q < n) ? g_deg[base + q] : 0;
        local += v[q];
    }
    int lane = t & 31, w = t >> 5;
    int xv = local;
#pragma unroll
    for (int off = 1; off < 32; off <<= 1) {
        int y = __shfl_up_sync(0xffffffffu, xv, off);
        if (lane >= off) xv += y;
    }
    __shared__ int wsum[8], wexcl[8];
    if (lane == 31) wsum[w] = xv;
    __syncthreads();
    if (t == 0) {
        int r = 0;
        for (int q = 0; q < 8; q++) { wexcl[q] = r; r += wsum[q]; }
        g_bsum[b] = r;
    }
    __syncthreads();
    int run = wexcl[w] + xv - local;
#pragma unroll
    for (int q = 0; q < 4; q++) {
        if (base + q < n) g_rowptr[base + q] = run;
        run += v[q];
    }
}

__global__ void kscan2(int n) {
    int r = 0;
    for (int b = 0; b < NBLK_SCAN; b++) { int s = g_bsum[b]; g_bsumx[b] = r; r += s; }
    g_rowptr[n] = r;
}

__global__ void kscan3(int n) {
    int i = blockIdx.x * blockDim.x + threadIdx.x;
    if (i < n) {
        int vv = g_rowptr[i] + g_bsumx[i / SCAN_TILE];
        g_rowptr[i] = vv;
        g_widx[i] = vv;
    }
}

__global__ void kscatter(const int* __restrict__ ei, int e) {
    int i = blockIdx.x * blockDim.x + threadIdx.x;
    if (i < e) {
        int src = ei[i];
        int dst = ei[e + i];
        int pos = atomicAdd(&g_widx[dst], 1);
        g_csr[pos] = src;
    }
}

// ---------------- fused gather + softmax + aggregate + bias + residual + LN + ReLU ----------------
// one block (128 threads) per dst node. threads 0..95 own output channels.
#define CHUNK 128
__global__ void __launch_bounds__(128) kmain(const float* __restrict__ x,
                                             const float* __restrict__ bias,
                                             const float* __restrict__ gamma,
                                             const float* __restrict__ beta,
                                             float* __restrict__ out, int n) {
    int i = blockIdx.x;
    int t = threadIdx.x;
    __shared__ float ws[CHUNK][NH];
    __shared__ int   ss[CHUNK];
    __shared__ float adst_sh[NH];
    __shared__ float rs[4], rq[4];

    int row0 = g_rowptr[i];
    int deg  = g_rowptr[i + 1] - row0;

    if (t < NH) adst_sh[t] = g_adst[i * NH + t];
    __syncthreads();

    int head = (t < C) ? (t / CH) : 0;
    float acc = 0.f;
    float ssum = 0.f;

    for (int base = 0; base < deg; base += CHUNK) {
        int cnt = min(CHUNK, deg - base);
        // producer: per-edge weights (4 heads), exp(leakyrelu(a_src[j]+a_dst[i]))
        for (int j = t; j < cnt; j += 128) {
            int src = g_csr[row0 + base + j];
            ss[j] = src;
            float4 as = *(const float4*)&g_asrc[src * NH];
            float e0 = as.x + adst_sh[0];
            float e1 = as.y + adst_sh[1];
            float e2 = as.z + adst_sh[2];
            float e3 = as.w + adst_sh[3];
            e0 = (e0 > 0.f) ? e0 : NEG_SLOPE * e0;
            e1 = (e1 > 0.f) ? e1 : NEG_SLOPE * e1;
            e2 = (e2 > 0.f) ? e2 : NEG_SLOPE * e2;
            e3 = (e3 > 0.f) ? e3 : NEG_SLOPE * e3;
            ws[j][0] = __expf(e0);
            ws[j][1] = __expf(e1);
            ws[j][2] = __expf(e2);
            ws[j][3] = __expf(e3);
        }
        __syncthreads();
        // consumer: coalesced gather of h[src] rows
        if (t < C) {
            for (int j = 0; j < cnt; j++) {
                float w = ws[j][head];
                ssum += w;
                acc += w * g_h[ss[j] * C + t];
            }
        }
        __syncthreads();
    }

    float outv = 0.f;
    if (t < C) {
        // self loop
        float e = g_asrc[i * NH + head] + adst_sh[head];
        e = (e > 0.f) ? e : NEG_SLOPE * e;
        float wself = __expf(e);
        ssum += wself;
        acc += wself * g_h[i * C + t];
        outv = acc / (ssum + 1e-16f) + bias[t] + x[i * C + t];
    }

    // LayerNorm over 96 channels
    float v1 = (t < C) ? outv : 0.f;
    float v2 = v1 * v1;
#pragma unroll
    for (int off = 16; off > 0; off >>= 1) {
        v1 += __shfl_down_sync(0xffffffffu, v1, off);
        v2 += __shfl_down_sync(0xffffffffu, v2, off);
    }
    int lane = t & 31, w = t >> 5;
    if (lane == 0) { rs[w] = v1; rq[w] = v2; }
    __syncthreads();
    float sum  = rs[0] + rs[1] + rs[2] + rs[3];
    float sumq = rq[0] + rq[1] + rq[2] + rq[3];
    float mu  = sum * (1.f / 96.f);
    float var = sumq * (1.f / 96.f) - mu * mu;
    float inv = rsqrtf(var + LN_EPS);
    if (t < C) {
        float y = (outv - mu) * inv * gamma[t] + beta[t];
        out[i * C + t] = fmaxf(y, 0.f);
    }
}

// ---------------- launch ----------------
extern "C" void kernel_launch(void* const* d_in, const int* in_sizes, int n_in,
                              void* d_out, int out_size) {
    const float* x        = (const float*)d_in[0];
    const int*   ei       = (const int*)d_in[1];
    const float* W        = (const float*)d_in[2];
    const float* att_src  = (const float*)d_in[3];
    const float* att_dst  = (const float*)d_in[4];
    const float* bias     = (const float*)d_in[5];
    const float* gamma    = (const float*)d_in[6];
    const float* beta     = (const float*)d_in[7];
    float* out = (float*)d_out;

    int n = in_sizes[0] / C;       // 50000
    int e = in_sizes[1] / 2;       // 800000

    kzero<<<(n + 255) / 256, 256>>>(n);
    kgemm<<<(n + BR - 1) / BR, 96>>>(x, W, n);
    kattn<<<(n * 32 + 255) / 256, 256>>>(att_src, att_dst, n);
    khist<<<(e + 255) / 256, 256>>>(ei, e);
    kscan1<<<NBLK_SCAN, 256>>>(n);
    kscan2<<<1, 1>>>(n);
    kscan3<<<(n + 255) / 256, 256>>>(n);
    kscatter<<<(e + 255) / 256, 256>>>(ei, e);
    kmain<<<n, 128>>>(x, bias, gamma, beta, out, n);
}

// round 3
// speedup vs baseline: 1.1375x; 1.1375x over previous
#include <cuda_runtime.h>
#include <math.h>

// Problem constants (fixed by reference: N=50000, E=800000, C=96, H=4, CH=24)
#define NMAX 50000
#define EMAX 800000
#define C 96
#define NH 4
#define CH 24
#define NEG_SLOPE 0.2f
#define LN_EPS 1e-5f

// ---------------- device scratch (static, no allocation) ----------------
__device__ float g_h[NMAX * C];        // 19.2 MB
__device__ float g_asrc[NMAX * NH];
__device__ float g_adst[NMAX * NH];
__device__ int   g_deg[NMAX];
__device__ int   g_rowptr[NMAX + 1];
__device__ int   g_widx[NMAX];
__device__ int   g_csr[EMAX];

#define SCAN_TILE 1024
#define NBLK_SCAN ((NMAX + SCAN_TILE - 1) / SCAN_TILE)   // 49
__device__ int g_bsum[NBLK_SCAN];
__device__ int g_bsumx[NBLK_SCAN];

// ---------------- zero degree counters ----------------
__global__ void kzero(int n) {
    int i = blockIdx.x * blockDim.x + threadIdx.x;
    if (i < n) g_deg[i] = 0;
}

// ---------------- GEMM h = x@W  + fused attention coefficients ----------------
// 192 threads: tc = t%24 (col group, 4 cols), tr = t/24 (row group, 3 rows).
// 24 rows per block. smem: 36.9KB (W) + 9.6KB (x) + 0.8KB (red) < 48KB.
// Epilogue computes a_src/a_dst from accumulators (no g_h re-read).
#define BR 24
__global__ void __launch_bounds__(192) kgemm(const float* __restrict__ x,
                                             const float* __restrict__ W,
                                             const float* __restrict__ att_src,
                                             const float* __restrict__ att_dst,
                                             int n) {
    __shared__ __align__(16) float Ws[96 * 96];   // 36864 B
    __shared__ float xs[BR][100];                 // 9600 B
    __shared__ float red[2][BR][NH];              // 768 B
    int t = threadIdx.x;
    for (int idx = t; idx < 96 * 96; idx += 192) Ws[idx] = W[idx];
    int r0 = blockIdx.x * BR;
    int rows = min(BR, n - r0);
    for (int idx = t; idx < rows * 96; idx += 192) {
        int r = idx / 96, c = idx % 96;
        xs[r][c] = x[(r0 + r) * 96 + c];
    }
    if (t < BR * NH) {
        red[0][t / NH][t % NH] = 0.f;
        red[1][t / NH][t % NH] = 0.f;
    }
    __syncthreads();

    int tc = t % 24;   // cols tc*4 .. tc*4+3
    int tr = t / 24;   // rows tr*3 .. tr*3+2
    float acc[3][4];
#pragma unroll
    for (int p = 0; p < 3; p++)
#pragma unroll
        for (int q = 0; q < 4; q++) acc[p][q] = 0.f;

#pragma unroll 4
    for (int k = 0; k < 96; k++) {
        float4 wv = *(const float4*)&Ws[k * 96 + tc * 4];
        float xv[3];
#pragma unroll
        for (int p = 0; p < 3; p++) xv[p] = xs[tr * 3 + p][k];
#pragma unroll
        for (int p = 0; p < 3; p++) {
            acc[p][0] += xv[p] * wv.x;
            acc[p][1] += xv[p] * wv.y;
            acc[p][2] += xv[p] * wv.z;
            acc[p][3] += xv[p] * wv.w;
        }
    }

    // store h
#pragma unroll
    for (int p = 0; p < 3; p++) {
        int gr = r0 + tr * 3 + p;
        if (gr < n) {
            float4 st = make_float4(acc[p][0], acc[p][1], acc[p][2], acc[p][3]);
            *(float4*)&g_h[gr * 96 + tc * 4] = st;
        }
    }

    // fused attention coefficients: att arrays are flat per-channel [96]
    int col0 = tc * 4;
    int head = tc / 6;                // all 4 cols in same head
    float4 asv = *(const float4*)&att_src[col0];
    float4 adv = *(const float4*)&att_dst[col0];
#pragma unroll
    for (int p = 0; p < 3; p++) {
        int lr = tr * 3 + p;
        if (lr < rows) {
            float ps = acc[p][0] * asv.x + acc[p][1] * asv.y + acc[p][2] * asv.z + acc[p][3] * asv.w;
            float pd = acc[p][0] * adv.x + acc[p][1] * adv.y + acc[p][2] * adv.z + acc[p][3] * adv.w;
            atomicAdd(&red[0][lr][head], ps);
            atomicAdd(&red[1][lr][head], pd);
        }
    }
    __syncthreads();
    if (t < 2 * BR * NH) {
        int which = t / (BR * NH);
        int rem = t % (BR * NH);
        int lr = rem / NH, hh = rem % NH;
        if (lr < rows) {
            float v = red[which][lr][hh];
            if (which == 0) g_asrc[(r0 + lr) * NH + hh] = v;
            else            g_adst[(r0 + lr) * NH + hh] = v;
        }
    }
}

// ---------------- CSR build ----------------
__global__ void khist(const int* __restrict__ ei, int e4) {
    int i = blockIdx.x * blockDim.x + threadIdx.x;
    if (i < e4) {
        int4 d = ((const int4*)ei)[i];   // ei already offset to dst row
        atomicAdd(&g_deg[d.x], 1);
        atomicAdd(&g_deg[d.y], 1);
        atomicAdd(&g_deg[d.z], 1);
        atomicAdd(&g_deg[d.w], 1);
    }
}

__global__ void kscan1(int n) {
    int b = blockIdx.x, t = threadIdx.x;
    int base = b * SCAN_TILE + t * 4;
    int v[4];
    int local = 0;
#pragma unroll
    for (int q = 0; q < 4; q++) {
        v[q] = (base + q < n) ? g_deg[base + q] : 0;
        local += v[q];
    }
    int lane = t & 31, w = t >> 5;
    int xv = local;
#pragma unroll
    for (int off = 1; off < 32; off <<= 1) {
        int y = __shfl_up_sync(0xffffffffu, xv, off);
        if (lane >= off) xv += y;
    }
    __shared__ int wsum[8], wexcl[8];
    if (lane == 31) wsum[w] = xv;
    __syncthreads();
    if (t == 0) {
        int r = 0;
        for (int q = 0; q < 8; q++) { wexcl[q] = r; r += wsum[q]; }
        g_bsum[b] = r;
    }
    __syncthreads();
    int run = wexcl[w] + xv - local;
#pragma unroll
    for (int q = 0; q < 4; q++) {
        if (base + q < n) g_rowptr[base + q] = run;
        run += v[q];
    }
}

// parallel scan over the 49 block sums (single block, 64 threads)
__global__ void kscan2(int n) {
    __shared__ int sh[64];
    int t = threadIdx.x;
    int v = (t < NBLK_SCAN) ? g_bsum[t] : 0;
    sh[t] = v;
    __syncthreads();
#pragma unroll
    for (int off = 1; off < 64; off <<= 1) {
        int y = (t >= off) ? sh[t - off] : 0;
        __syncthreads();
        sh[t] += y;
        __syncthreads();
    }
    if (t < NBLK_SCAN) g_bsumx[t] = sh[t] - v;   // exclusive
    if (t == 63) g_rowptr[n] = sh[63];
}

__global__ void kscan3(int n) {
    int i = blockIdx.x * blockDim.x + threadIdx.x;
    if (i < n) {
        int vv = g_rowptr[i] + g_bsumx[i / SCAN_TILE];
        g_rowptr[i] = vv;
        g_widx[i] = vv;
    }
}

__global__ void kscatter(const int* __restrict__ ei, int e) {
    int i = blockIdx.x * blockDim.x + threadIdx.x;
    int e4 = e >> 2;
    if (i < e4) {
        int4 s = ((const int4*)ei)[i];
        int4 d = ((const int4*)(ei + e))[i];
        int p0 = atomicAdd(&g_widx[d.x], 1); g_csr[p0] = s.x;
        int p1 = atomicAdd(&g_widx[d.y], 1); g_csr[p1] = s.y;
        int p2 = atomicAdd(&g_widx[d.z], 1); g_csr[p2] = s.z;
        int p3 = atomicAdd(&g_widx[d.w], 1); g_csr[p3] = s.w;
    }
}

// ---------------- fused gather + softmax + aggregate + bias + residual + LN + ReLU ----------------
// one block (96 threads) per dst node; every thread owns one output channel.
#define CHUNK 96
__global__ void __launch_bounds__(96) kmain(const float* __restrict__ x,
                                            const float* __restrict__ bias,
                                            const float* __restrict__ gamma,
                                            const float* __restrict__ beta,
                                            float* __restrict__ out, int n) {
    int i = blockIdx.x;
    int t = threadIdx.x;
    __shared__ float ws[CHUNK][NH];
    __shared__ int   ss[CHUNK];
    __shared__ float adst_sh[NH];
    __shared__ float rs[3], rq[3];

    int row0 = g_rowptr[i];
    int deg  = g_rowptr[i + 1] - row0;

    if (t < NH) adst_sh[t] = g_adst[i * NH + t];
    __syncthreads();

    int head = t / CH;
    float acc = 0.f;
    float ssum = 0.f;

    for (int base = 0; base < deg; base += CHUNK) {
        int cnt = min(CHUNK, deg - base);
        // producer: per-edge weights (4 heads)
        if (t < cnt) {
            int src = g_csr[row0 + base + t];
            ss[t] = src;
            float4 as = *(const float4*)&g_asrc[src * NH];
            float e0 = as.x + adst_sh[0];
            float e1 = as.y + adst_sh[1];
            float e2 = as.z + adst_sh[2];
            float e3 = as.w + adst_sh[3];
            e0 = (e0 > 0.f) ? e0 : NEG_SLOPE * e0;
            e1 = (e1 > 0.f) ? e1 : NEG_SLOPE * e1;
            e2 = (e2 > 0.f) ? e2 : NEG_SLOPE * e2;
            e3 = (e3 > 0.f) ? e3 : NEG_SLOPE * e3;
            ws[t][0] = __expf(e0);
            ws[t][1] = __expf(e1);
            ws[t][2] = __expf(e2);
            ws[t][3] = __expf(e3);
        }
        __syncthreads();
        // consumer: coalesced gather of h[src], unrolled x4 for MLP
        int j = 0;
        for (; j + 3 < cnt; j += 4) {
            float w0 = ws[j + 0][head], w1 = ws[j + 1][head];
            float w2 = ws[j + 2][head], w3 = ws[j + 3][head];
            float h0 = g_h[ss[j + 0] * C + t];
            float h1 = g_h[ss[j + 1] * C + t];
            float h2 = g_h[ss[j + 2] * C + t];
            float h3 = g_h[ss[j + 3] * C + t];
            ssum += (w0 + w1) + (w2 + w3);
            acc += w0 * h0;
            acc += w1 * h1;
            acc += w2 * h2;
            acc += w3 * h3;
        }
        for (; j < cnt; j++) {
            float w = ws[j][head];
            ssum += w;
            acc += w * g_h[ss[j] * C + t];
        }
        __syncthreads();
    }

    // self loop
    float e = g_asrc[i * NH + head] + adst_sh[head];
    e = (e > 0.f) ? e : NEG_SLOPE * e;
    float wself = __expf(e);
    ssum += wself;
    acc += wself * g_h[i * C + t];
    float outv = acc / (ssum + 1e-16f) + bias[t] + x[i * C + t];

    // LayerNorm over 96 channels
    float v1 = outv;
    float v2 = v1 * v1;
#pragma unroll
    for (int off = 16; off > 0; off >>= 1) {
        v1 += __shfl_down_sync(0xffffffffu, v1, off);
        v2 += __shfl_down_sync(0xffffffffu, v2, off);
    }
    int lane = t & 31, w = t >> 5;
    if (lane == 0) { rs[w] = v1; rq[w] = v2; }
    __syncthreads();
    float sum  = rs[0] + rs[1] + rs[2];
    float sumq = rq[0] + rq[1] + rq[2];
    float mu  = sum * (1.f / 96.f);
    float var = sumq * (1.f / 96.f) - mu * mu;
    float inv = rsqrtf(var + LN_EPS);
    float y = (outv - mu) * inv * gamma[t] + beta[t];
    out[i * C + t] = fmaxf(y, 0.f);
}

// ---------------- launch ----------------
extern "C" void kernel_launch(void* const* d_in, const int* in_sizes, int n_in,
                              void* d_out, int out_size) {
    const float* x        = (const float*)d_in[0];
    const int*   ei       = (const int*)d_in[1];
    const float* W        = (const float*)d_in[2];
    const float* att_src  = (const float*)d_in[3];
    const float* att_dst  = (const float*)d_in[4];
    const float* bias     = (const float*)d_in[5];
    const float* gamma    = (const float*)d_in[6];
    const float* beta     = (const float*)d_in[7];
    float* out = (float*)d_out;

    int n = in_sizes[0] / C;       // 50000
    int e = in_sizes[1] / 2;       // 800000
    int e4 = e >> 2;

    kzero<<<(n + 255) / 256, 256>>>(n);
    kgemm<<<(n + BR - 1) / BR, 192>>>(x, W, att_src, att_dst, n);
    khist<<<(e4 + 255) / 256, 256>>>(ei + e, e4);
    kscan1<<<NBLK_SCAN, 256>>>(n);
    kscan2<<<1, 64>>>(n);
    kscan3<<<(n + 255) / 256, 256>>>(n);
    kscatter<<<(e4 + 255) / 256, 256>>>(ei, e);
    kmain<<<n, 96>>>(x, bias, gamma, beta, out, n);
}

// round 4
// speedup vs baseline: 1.2124x; 1.0658x over previous
#include <cuda_runtime.h>
#include <math.h>

// Problem constants (fixed by reference: N=50000, E=800000, C=96, H=4, CH=24)
#define NMAX 50000
#define EMAX 800000
#define C 96
#define NH 4
#define CH 24
#define NEG_SLOPE 0.2f
#define LN_EPS 1e-5f

// ---------------- device scratch (static, no allocation) ----------------
__device__ float g_h[NMAX * C];        // 19.2 MB
__device__ float g_asrc[NMAX * NH];
__device__ float g_adst[NMAX * NH];
__device__ int   g_deg[NMAX];
__device__ int   g_rowptr[NMAX + 1];
__device__ int   g_widx[NMAX];
__device__ int   g_csr[EMAX];

#define SCAN_TILE 1024
#define NBLK_SCAN ((NMAX + SCAN_TILE - 1) / SCAN_TILE)   // 49
__device__ int g_bsum[NBLK_SCAN];
__device__ int g_bsumx[NBLK_SCAN];

// ---------------- zero degree counters ----------------
__global__ void kzero(int n) {
    int i = blockIdx.x * blockDim.x + threadIdx.x;
    if (i < n) g_deg[i] = 0;
}

// ================= fused GEMM(+attn coeffs) / CSR-stage kernels =================
// GEMM block: 64 rows x 96 cols, 192 threads, micro-tile 8 rows x 4 cols.
// x slice stored TRANSPOSED in smem (xs[k][row]) -> 3x LDS.128 per 32 FMAs
// => FFMA-pipe bound, not smem-crossbar bound.
// W loaded in two k=48 slices to stay under 48KB static smem.
#define GR 64
#define GEMM_THREADS 192
#define XS_PAD 68   // 68*4B = 272B row stride: 16B-aligned for float4 reads

__device__ __forceinline__ void gemm_block(int gb,
                                           const float* __restrict__ x,
                                           const float* __restrict__ W,
                                           const float* __restrict__ att_src,
                                           const float* __restrict__ att_dst,
                                           int n,
                                           float* Ws /*48*96*/,
                                           float (*xs)[XS_PAD] /*48 x pad*/,
                                           float* red /*2*GR*NH*/) {
    int t = threadIdx.x;
    int r0 = gb * GR;
    int rows = min(GR, n - r0);

    for (int idx = t; idx < 2 * GR * NH; idx += GEMM_THREADS) red[idx] = 0.f;

    int tc = t % 24;   // cols tc*4 .. tc*4+3
    int tr = t / 24;   // rows tr*8 .. tr*8+7
    float acc[8][4];
#pragma unroll
    for (int p = 0; p < 8; p++)
#pragma unroll
        for (int q = 0; q < 4; q++) acc[p][q] = 0.f;

    for (int ks = 0; ks < 96; ks += 48) {
        // load W slice [48][96], coalesced
        for (int idx = t; idx < 48 * 96; idx += GEMM_THREADS)
            Ws[idx] = W[(ks + idx / 96) * 96 + idx % 96];
        // load x slice transposed: xs[k][row] = x[(r0+row)*96 + ks + k]
        for (int idx = t; idx < rows * 48; idx += GEMM_THREADS) {
            int r = idx / 48, k = idx % 48;
            xs[k][r] = x[(r0 + r) * 96 + ks + k];
        }
        __syncthreads();
#pragma unroll 4
        for (int k = 0; k < 48; k++) {
            float4 wv = *(const float4*)&Ws[k * 96 + tc * 4];
            float4 xa = *(const float4*)&xs[k][tr * 8];
            float4 xb = *(const float4*)&xs[k][tr * 8 + 4];
            float xv[8] = {xa.x, xa.y, xa.z, xa.w, xb.x, xb.y, xb.z, xb.w};
#pragma unroll
            for (int p = 0; p < 8; p++) {
                acc[p][0] += xv[p] * wv.x;
                acc[p][1] += xv[p] * wv.y;
                acc[p][2] += xv[p] * wv.z;
                acc[p][3] += xv[p] * wv.w;
            }
        }
        __syncthreads();
    }

    // store h
#pragma unroll
    for (int p = 0; p < 8; p++) {
        int gr = r0 + tr * 8 + p;
        if (gr < n) {
            float4 st = make_float4(acc[p][0], acc[p][1], acc[p][2], acc[p][3]);
            *(float4*)&g_h[gr * 96 + tc * 4] = st;
        }
    }

    // fused attention coefficients from resident accumulators
    int col0 = tc * 4;
    int head = tc / 6;
    float4 asv = *(const float4*)&att_src[col0];
    float4 adv = *(const float4*)&att_dst[col0];
#pragma unroll
    for (int p = 0; p < 8; p++) {
        int lr = tr * 8 + p;
        if (lr < rows) {
            float ps = acc[p][0] * asv.x + acc[p][1] * asv.y + acc[p][2] * asv.z + acc[p][3] * asv.w;
            float pd = acc[p][0] * adv.x + acc[p][1] * adv.y + acc[p][2] * adv.z + acc[p][3] * adv.w;
            atomicAdd(&red[(0 * GR + lr) * NH + head], ps);
            atomicAdd(&red[(1 * GR + lr) * NH + head], pd);
        }
    }
    __syncthreads();
    for (int idx = t; idx < 2 * GR * NH; idx += GEMM_THREADS) {
        int which = idx / (GR * NH);
        int rem = idx % (GR * NH);
        int lr = rem / NH, hh = rem % NH;
        if (lr < rows) {
            float v = red[idx];
            if (which == 0) g_asrc[(r0 + lr) * NH + hh] = v;
            else            g_adst[(r0 + lr) * NH + hh] = v;
        }
    }
}

// fused1: gemm rows [0, GB1*GR) + histogram of dst
__global__ void __launch_bounds__(GEMM_THREADS) kfused1(const float* __restrict__ x,
                                                        const float* __restrict__ W,
                                                        const float* __restrict__ att_src,
                                                        const float* __restrict__ att_dst,
                                                        int n, int GB1,
                                                        const int* __restrict__ dst, int e) {
    __shared__ __align__(16) float Ws[48 * 96];
    __shared__ __align__(16) float xs[48][XS_PAD];
    __shared__ float red[2 * GR * NH];
    if ((int)blockIdx.x < GB1) {
        gemm_block(blockIdx.x, x, W, att_src, att_dst, n, Ws, xs, red);
    } else {
        int e4 = e >> 2;
        int i = (blockIdx.x - GB1) * GEMM_THREADS + threadIdx.x;
        if (i < e4) {
            int4 d = ((const int4*)dst)[i];
            atomicAdd(&g_deg[d.x], 1);
            atomicAdd(&g_deg[d.y], 1);
            atomicAdd(&g_deg[d.z], 1);
            atomicAdd(&g_deg[d.w], 1);
        }
        if (i == e4) {
            for (int q = e4 * 4; q < e; q++) atomicAdd(&g_deg[dst[q]], 1);
        }
    }
}

// fused2: gemm rows [GB1*GR, n) + scatter src ids into CSR
__global__ void __launch_bounds__(GEMM_THREADS) kfused2(const float* __restrict__ x,
                                                        const float* __restrict__ W,
                                                        const float* __restrict__ att_src,
                                                        const float* __restrict__ att_dst,
                                                        int n, int GB1, int GB2,
                                                        const int* __restrict__ ei, int e) {
    __shared__ __align__(16) float Ws[48 * 96];
    __shared__ __align__(16) float xs[48][XS_PAD];
    __shared__ float red[2 * GR * NH];
    if ((int)blockIdx.x < GB2) {
        gemm_block(GB1 + blockIdx.x, x, W, att_src, att_dst, n, Ws, xs, red);
    } else {
        int e4 = e >> 2;
        int i = (blockIdx.x - GB2) * GEMM_THREADS + threadIdx.x;
        if (i < e4) {
            int4 s = ((const int4*)ei)[i];
            int4 d = ((const int4*)(ei + e))[i];
            int p0 = atomicAdd(&g_widx[d.x], 1); g_csr[p0] = s.x;
            int p1 = atomicAdd(&g_widx[d.y], 1); g_csr[p1] = s.y;
            int p2 = atomicAdd(&g_widx[d.z], 1); g_csr[p2] = s.z;
            int p3 = atomicAdd(&g_widx[d.w], 1); g_csr[p3] = s.w;
        }
        if (i == e4) {
            for (int q = e4 * 4; q < e; q++) {
                int pos = atomicAdd(&g_widx[ei[e + q]], 1);
                g_csr[pos] = ei[q];
            }
        }
    }
}

// ---------------- scans ----------------
__global__ void kscan1(int n) {
    int b = blockIdx.x, t = threadIdx.x;
    int base = b * SCAN_TILE + t * 4;
    int v[4];
    int local = 0;
#pragma unroll
    for (int q = 0; q < 4; q++) {
        v[q] = (base + q < n) ? g_deg[base + q] : 0;
        local += v[q];
    }
    int lane = t & 31, w = t >> 5;
    int xv = local;
#pragma unroll
    for (int off = 1; off < 32; off <<= 1) {
        int y = __shfl_up_sync(0xffffffffu, xv, off);
        if (lane >= off) xv += y;
    }
    __shared__ int wsum[8], wexcl[8];
    if (lane == 31) wsum[w] = xv;
    __syncthreads();
    if (t == 0) {
        int r = 0;
        for (int q = 0; q < 8; q++) { wexcl[q] = r; r += wsum[q]; }
        g_bsum[b] = r;
    }
    __syncthreads();
    int run = wexcl[w] + xv - local;
#pragma unroll
    for (int q = 0; q < 4; q++) {
        if (base + q < n) g_rowptr[base + q] = run;
        run += v[q];
    }
}

__global__ void kscan2(int n) {
    __shared__ int sh[64];
    int t = threadIdx.x;
    int v = (t < NBLK_SCAN) ? g_bsum[t] : 0;
    sh[t] = v;
    __syncthreads();
#pragma unroll
    for (int off = 1; off < 64; off <<= 1) {
        int y = (t >= off) ? sh[t - off] : 0;
        __syncthreads();
        sh[t] += y;
        __syncthreads();
    }
    if (t < NBLK_SCAN) g_bsumx[t] = sh[t] - v;   // exclusive
    if (t == 63) g_rowptr[n] = sh[63];
}

__global__ void kscan3(int n) {
    int i = blockIdx.x * blockDim.x + threadIdx.x;
    if (i < n) {
        int vv = g_rowptr[i] + g_bsumx[i / SCAN_TILE];
        g_rowptr[i] = vv;
        g_widx[i] = vv;
    }
}

// ---------------- fused gather + softmax + aggregate + bias + residual + LN + ReLU ----------------
#define CHUNK 96
__global__ void __launch_bounds__(96) kmain(const float* __restrict__ x,
                                            const float* __restrict__ bias,
                                            const float* __restrict__ gamma,
                                            const float* __restrict__ beta,
                                            float* __restrict__ out, int n) {
    int i = blockIdx.x;
    int t = threadIdx.x;
    __shared__ float ws[CHUNK][NH];
    __shared__ int   ss[CHUNK];
    __shared__ float adst_sh[NH];
    __shared__ float rs[3], rq[3];

    int row0 = g_rowptr[i];
    int deg  = g_rowptr[i + 1] - row0;

    if (t < NH) adst_sh[t] = g_adst[i * NH + t];
    __syncthreads();

    int head = t / CH;
    float acc = 0.f;
    float ssum = 0.f;

    for (int base = 0; base < deg; base += CHUNK) {
        int cnt = min(CHUNK, deg - base);
        if (t < cnt) {
            int src = __ldg(&g_csr[row0 + base + t]);
            ss[t] = src;
            float4 as = __ldg((const float4*)&g_asrc[src * NH]);
            float e0 = as.x + adst_sh[0];
            float e1 = as.y + adst_sh[1];
            float e2 = as.z + adst_sh[2];
            float e3 = as.w + adst_sh[3];
            e0 = (e0 > 0.f) ? e0 : NEG_SLOPE * e0;
            e1 = (e1 > 0.f) ? e1 : NEG_SLOPE * e1;
            e2 = (e2 > 0.f) ? e2 : NEG_SLOPE * e2;
            e3 = (e3 > 0.f) ? e3 : NEG_SLOPE * e3;
            ws[t][0] = __expf(e0);
            ws[t][1] = __expf(e1);
            ws[t][2] = __expf(e2);
            ws[t][3] = __expf(e3);
        }
        __syncthreads();
        int j = 0;
        for (; j + 3 < cnt; j += 4) {
            float w0 = ws[j + 0][head], w1 = ws[j + 1][head];
            float w2 = ws[j + 2][head], w3 = ws[j + 3][head];
            float h0 = __ldg(&g_h[ss[j + 0] * C + t]);
            float h1 = __ldg(&g_h[ss[j + 1] * C + t]);
            float h2 = __ldg(&g_h[ss[j + 2] * C + t]);
            float h3 = __ldg(&g_h[ss[j + 3] * C + t]);
            ssum += (w0 + w1) + (w2 + w3);
            acc += w0 * h0;
            acc += w1 * h1;
            acc += w2 * h2;
            acc += w3 * h3;
        }
        for (; j < cnt; j++) {
            float w = ws[j][head];
            ssum += w;
            acc += w * __ldg(&g_h[ss[j] * C + t]);
        }
        __syncthreads();
    }

    // self loop
    float e = g_asrc[i * NH + head] + adst_sh[head];
    e = (e > 0.f) ? e : NEG_SLOPE * e;
    float wself = __expf(e);
    ssum += wself;
    acc += wself * g_h[i * C + t];
    float outv = acc / (ssum + 1e-16f) + bias[t] + x[i * C + t];

    // LayerNorm over 96 channels
    float v1 = outv;
    float v2 = v1 * v1;
#pragma unroll
    for (int off = 16; off > 0; off >>= 1) {
        v1 += __shfl_down_sync(0xffffffffu, v1, off);
        v2 += __shfl_down_sync(0xffffffffu, v2, off);
    }
    int lane = t & 31, w = t >> 5;
    if (lane == 0) { rs[w] = v1; rq[w] = v2; }
    __syncthreads();
    float sum  = rs[0] + rs[1] + rs[2];
    float sumq = rq[0] + rq[1] + rq[2];
    float mu  = sum * (1.f / 96.f);
    float var = sumq * (1.f / 96.f) - mu * mu;
    float inv = rsqrtf(var + LN_EPS);
    float y = (outv - mu) * inv * gamma[t] + beta[t];
    out[i * C + t] = fmaxf(y, 0.f);
}

// ---------------- launch ----------------
extern "C" void kernel_launch(void* const* d_in, const int* in_sizes, int n_in,
                              void* d_out, int out_size) {
    const float* x        = (const float*)d_in[0];
    const int*   ei       = (const int*)d_in[1];
    const float* W        = (const float*)d_in[2];
    const float* att_src  = (const float*)d_in[3];
    const float* att_dst  = (const float*)d_in[4];
    const float* bias     = (const float*)d_in[5];
    const float* gamma    = (const float*)d_in[6];
    const float* beta     = (const float*)d_in[7];
    float* out = (float*)d_out;

    int n = in_sizes[0] / C;       // 50000
    int e = in_sizes[1] / 2;       // 800000
    int e4 = e >> 2;

    int gemm_blocks = (n + GR - 1) / GR;          // 782
    int GB1 = (gemm_blocks + 1) / 2;              // 391
    int GB2 = gemm_blocks - GB1;                  // 391
    int csr_blocks = (e4 + GEMM_THREADS) / GEMM_THREADS;  // covers e4 + tail thread

    kzero<<<(n + 255) / 256, 256>>>(n);
    kfused1<<<GB1 + csr_blocks, GEMM_THREADS>>>(x, W, att_src, att_dst, n, GB1, ei + e, e);
    kscan1<<<NBLK_SCAN, 256>>>(n);
    kscan2<<<1, 64>>>(n);
    kscan3<<<(n + 255) / 256, 256>>>(n);
    kfused2<<<GB2 + csr_blocks, GEMM_THREADS>>>(x, W, att_src, att_dst, n, GB1, GB2, ei, e);
    kmain<<<n, 96>>>(x, bias, gamma, beta, out, n);
}

// round 7
// speedup vs baseline: 1.5115x; 1.2468x over previous
#include <cuda_runtime.h>
#include <math.h>

// Problem constants (fixed by reference: N=50000, E=800000, C=96, H=4, CH=24)
#define NMAX 50000
#define EMAX 800000
#define C 96
#define NH 4
#define CH 24
#define NEG_SLOPE 0.2f
#define LN_EPS 1e-5f

// ---------------- device scratch (static, no allocation) ----------------
__device__ float g_h[NMAX * C];        // 19.2 MB
__device__ float g_asrc[NMAX * NH];
__device__ float g_adst[NMAX * NH];
__device__ int   g_deg[NMAX];
__device__ int   g_rowptr[NMAX + 1];
__device__ int   g_widx[NMAX];
__device__ int   g_csr[EMAX];

#define SCAN_TILE 1024
#define NBLK_SCAN ((NMAX + SCAN_TILE - 1) / SCAN_TILE)   // 49
__device__ int g_bsum[NBLK_SCAN];

// ---------------- zero counters (deg + scan flags) ----------------
__global__ void kzero(int n) {
    int i = blockIdx.x * blockDim.x + threadIdx.x;
    if (i < n) g_deg[i] = 0;
    if (i < NBLK_SCAN) g_bsum[i] = 0;
}

// ================= fused GEMM(+attn coeffs) / CSR-stage kernels =================
#define GR 64
#define GEMM_THREADS 192
#define XS_PAD 68

__device__ __forceinline__ void gemm_block(int gb,
                                           const float* __restrict__ x,
                                           const float* __restrict__ W,
                                           const float* __restrict__ att_src,
                                           const float* __restrict__ att_dst,
                                           int n,
                                           float* Ws, float (*xs)[XS_PAD], float* red) {
    int t = threadIdx.x;
    int r0 = gb * GR;
    int rows = min(GR, n - r0);

    for (int idx = t; idx < 2 * GR * NH; idx += GEMM_THREADS) red[idx] = 0.f;

    int tc = t % 24;
    int tr = t / 24;
    float acc[8][4];
#pragma unroll
    for (int p = 0; p < 8; p++)
#pragma unroll
        for (int q = 0; q < 4; q++) acc[p][q] = 0.f;

    for (int ks = 0; ks < 96; ks += 48) {
        for (int idx = t; idx < 48 * 96; idx += GEMM_THREADS)
            Ws[idx] = W[(ks + idx / 96) * 96 + idx % 96];
        for (int idx = t; idx < rows * 48; idx += GEMM_THREADS) {
            int r = idx / 48, k = idx % 48;
            xs[k][r] = x[(r0 + r) * 96 + ks + k];
        }
        __syncthreads();
#pragma unroll 4
        for (int k = 0; k < 48; k++) {
            float4 wv = *(const float4*)&Ws[k * 96 + tc * 4];
            float4 xa = *(const float4*)&xs[k][tr * 8];
            float4 xb = *(const float4*)&xs[k][tr * 8 + 4];
            float xv[8] = {xa.x, xa.y, xa.z, xa.w, xb.x, xb.y, xb.z, xb.w};
#pragma unroll
            for (int p = 0; p < 8; p++) {
                acc[p][0] += xv[p] * wv.x;
                acc[p][1] += xv[p] * wv.y;
                acc[p][2] += xv[p] * wv.z;
                acc[p][3] += xv[p] * wv.w;
            }
        }
        __syncthreads();
    }

#pragma unroll
    for (int p = 0; p < 8; p++) {
        int gr = r0 + tr * 8 + p;
        if (gr < n) {
            float4 st = make_float4(acc[p][0], acc[p][1], acc[p][2], acc[p][3]);
            *(float4*)&g_h[gr * 96 + tc * 4] = st;
        }
    }

    int col0 = tc * 4;
    int head = tc / 6;
    float4 asv = *(const float4*)&att_src[col0];
    float4 adv = *(const float4*)&att_dst[col0];
#pragma unroll
    for (int p = 0; p < 8; p++) {
        int lr = tr * 8 + p;
        if (lr < rows) {
            float ps = acc[p][0] * asv.x + acc[p][1] * asv.y + acc[p][2] * asv.z + acc[p][3] * asv.w;
            float pd = acc[p][0] * adv.x + acc[p][1] * adv.y + acc[p][2] * adv.z + acc[p][3] * adv.w;
            atomicAdd(&red[(0 * GR + lr) * NH + head], ps);
            atomicAdd(&red[(1 * GR + lr) * NH + head], pd);
        }
    }
    __syncthreads();
    for (int idx = t; idx < 2 * GR * NH; idx += GEMM_THREADS) {
        int which = idx / (GR * NH);
        int rem = idx % (GR * NH);
        int lr = rem / NH, hh = rem % NH;
        if (lr < rows) {
            float v = red[idx];
            if (which == 0) g_asrc[(r0 + lr) * NH + hh] = v;
            else            g_adst[(r0 + lr) * NH + hh] = v;
        }
    }
}

__global__ void __launch_bounds__(GEMM_THREADS) kfused1(const float* __restrict__ x,
                                                        const float* __restrict__ W,
                                                        const float* __restrict__ att_src,
                                                        const float* __restrict__ att_dst,
                                                        int n, int GB1,
                                                        const int* __restrict__ dst, int e) {
    __shared__ __align__(16) float Ws[48 * 96];
    __shared__ __align__(16) float xs[48][XS_PAD];
    __shared__ float red[2 * GR * NH];
    if ((int)blockIdx.x < GB1) {
        gemm_block(blockIdx.x, x, W, att_src, att_dst, n, Ws, xs, red);
    } else {
        int e4 = e >> 2;
        int i = (blockIdx.x - GB1) * GEMM_THREADS + threadIdx.x;
        if (i < e4) {
            int4 d = ((const int4*)dst)[i];
            atomicAdd(&g_deg[d.x], 1);
            atomicAdd(&g_deg[d.y], 1);
            atomicAdd(&g_deg[d.z], 1);
            atomicAdd(&g_deg[d.w], 1);
        }
        if (i == e4) {
            for (int q = e4 * 4; q < e; q++) atomicAdd(&g_deg[dst[q]], 1);
        }
    }
}

__global__ void __launch_bounds__(GEMM_THREADS) kfused2(const float* __restrict__ x,
                                                        const float* __restrict__ W,
                                                        const float* __restrict__ att_src,
                                                        const float* __restrict__ att_dst,
                                                        int n, int GB1, int GB2,
                                                        const int* __restrict__ ei, int e) {
    __shared__ __align__(16) float Ws[48 * 96];
    __shared__ __align__(16) float xs[48][XS_PAD];
    __shared__ float red[2 * GR * NH];
    if ((int)blockIdx.x < GB2) {
        gemm_block(GB1 + blockIdx.x, x, W, att_src, att_dst, n, Ws, xs, red);
    } else {
        int e4 = e >> 2;
        int i = (blockIdx.x - GB2) * GEMM_THREADS + threadIdx.x;
        if (i < e4) {
            int4 s = ((const int4*)ei)[i];
            int4 d = ((const int4*)(ei + e))[i];
            int p0 = atomicAdd(&g_widx[d.x], 1); g_csr[p0] = s.x;
            int p1 = atomicAdd(&g_widx[d.y], 1); g_csr[p1] = s.y;
            int p2 = atomicAdd(&g_widx[d.z], 1); g_csr[p2] = s.z;
            int p3 = atomicAdd(&g_widx[d.w], 1); g_csr[p3] = s.w;
        }
        if (i == e4) {
            for (int q = e4 * 4; q < e; q++) {
                int pos = atomicAdd(&g_widx[ei[e + q]], 1);
                g_csr[pos] = ei[q];
            }
        }
    }
}

// ---------------- single-kernel scan with decoupled lookback ----------------
// 49 blocks, all resident in one wave. Each publishes its tile total with a
// flag bit; each polls all predecessors (with nanosleep backoff), reduces.
__global__ void __launch_bounds__(256) kscan(int n) {
    int b = blockIdx.x, t = threadIdx.x;
    __shared__ int wsum[8], wexcl[8];
    __shared__ int offsh;
    if (t == 0) offsh = 0;

    int base = b * SCAN_TILE + t * 4;
    int v[4];
    int local = 0;
#pragma unroll
    for (int q = 0; q < 4; q++) {
        v[q] = (base + q < n) ? g_deg[base + q] : 0;
        local += v[q];
    }
    int lane = t & 31, w = t >> 5;
    int xv = local;
#pragma unroll
    for (int off = 1; off < 32; off <<= 1) {
        int y = __shfl_up_sync(0xffffffffu, xv, off);
        if (lane >= off) xv += y;
    }
    if (lane == 31) wsum[w] = xv;
    __syncthreads();
    int r = 0;
    if (t == 0) {
        for (int q = 0; q < 8; q++) { wexcl[q] = r; r += wsum[q]; }
        atomicExch(&g_bsum[b], r | 0x80000000);   // publish with flag bit 31
    }
    __syncthreads();

    // lookback: thread t polls predecessor t
    int pv = 0;
    if (t < b) {
        int pub = atomicOr(&g_bsum[t], 0);
        while (pub >= 0) {
            __nanosleep(32);
            pub = atomicOr(&g_bsum[t], 0);
        }
        pv = pub & 0x7fffffff;
    }
#pragma unroll
    for (int off = 16; off > 0; off >>= 1) pv += __shfl_down_sync(0xffffffffu, pv, off);
    if (lane == 0 && pv != 0) atomicAdd(&offsh, pv);
    __syncthreads();
    int off0 = offsh;

    int run = off0 + wexcl[w] + xv - local;
#pragma unroll
    for (int q = 0; q < 4; q++) {
        if (base + q < n) { g_rowptr[base + q] = run; g_widx[base + q] = run; }
        run += v[q];
    }
    if (b == (int)gridDim.x - 1 && t == 0) {
        int tot = 0;
        for (int q = 0; q < 8; q++) tot += wsum[q];
        g_rowptr[n] = off0 + tot;
    }
}

// ---------------- kmain: warp-per-node, float4 channels ----------------
// 256 threads = 8 warps = 8 nodes per block. Lanes 0..23 own 4 channels each.
#define WCHUNK 32
__global__ void __launch_bounds__(256) kmain(const float* __restrict__ x,
                                             const float* __restrict__ bias,
                                             const float* __restrict__ gamma,
                                             const float* __restrict__ beta,
                                             float* __restrict__ out, int n) {
    int warp = threadIdx.x >> 5;
    int lane = threadIdx.x & 31;
    int i = blockIdx.x * 8 + warp;
    if (i >= n) return;

    __shared__ float ws[8][WCHUNK][NH];
    __shared__ int   ss[8][WCHUNK];

    int row0 = __ldg(&g_rowptr[i]);
    int deg  = __ldg(&g_rowptr[i + 1]) - row0;
    float4 ad = __ldg((const float4*)&g_adst[i * NH]);

    int cidx = (lane < 24) ? lane : 0;
    int head = cidx / 6;
    const float4* h4 = (const float4*)g_h;

    float4 acc = make_float4(0.f, 0.f, 0.f, 0.f);
    float ssum = 0.f;

    for (int bse = 0; bse < deg; bse += WCHUNK) {
        int cnt = min(WCHUNK, deg - bse);
        if (lane < cnt) {
            int src = __ldg(&g_csr[row0 + bse + lane]);
            ss[warp][lane] = src;
            float4 as = __ldg((const float4*)&g_asrc[src * NH]);
            float e0 = as.x + ad.x, e1 = as.y + ad.y, e2 = as.z + ad.z, e3 = as.w + ad.w;
            e0 = (e0 > 0.f) ? e0 : NEG_SLOPE * e0;
            e1 = (e1 > 0.f) ? e1 : NEG_SLOPE * e1;
            e2 = (e2 > 0.f) ? e2 : NEG_SLOPE * e2;
            e3 = (e3 > 0.f) ? e3 : NEG_SLOPE * e3;
            ws[warp][lane][0] = __expf(e0);
            ws[warp][lane][1] = __expf(e1);
            ws[warp][lane][2] = __expf(e2);
            ws[warp][lane][3] = __expf(e3);
        }
        __syncwarp();
        if (lane < 24) {
#pragma unroll 4
            for (int j = 0; j < cnt; j++) {
                float wv = ws[warp][j][head];
                float4 h = __ldg(&h4[ss[warp][j] * 24 + lane]);
                ssum += wv;
                acc.x += wv * h.x;
                acc.y += wv * h.y;
                acc.z += wv * h.z;
                acc.w += wv * h.w;
            }
        }
        __syncwarp();
    }

    // self loop + bias + residual
    float4 o = make_float4(0.f, 0.f, 0.f, 0.f);
    if (lane < 24) {
        float4 asi = __ldg((const float4*)&g_asrc[i * NH]);
        float es[4];
        es[0] = asi.x + ad.x; es[1] = asi.y + ad.y; es[2] = asi.z + ad.z; es[3] = asi.w + ad.w;
#pragma unroll
        for (int q = 0; q < 4; q++) es[q] = (es[q] > 0.f) ? es[q] : NEG_SLOPE * es[q];
        float wself = __expf(es[head]);
        float4 hi = __ldg(&h4[i * 24 + lane]);
        ssum += wself;
        acc.x += wself * hi.x; acc.y += wself * hi.y;
        acc.z += wself * hi.z; acc.w += wself * hi.w;
        float inv_s = 1.f / (ssum + 1e-16f);
        float4 bv = __ldg((const float4*)&bias[lane * 4]);
        float4 xv = __ldg(&((const float4*)x)[i * 24 + lane]);
        o.x = acc.x * inv_s + bv.x + xv.x;
        o.y = acc.y * inv_s + bv.y + xv.y;
        o.z = acc.z * inv_s + bv.z + xv.z;
        o.w = acc.w * inv_s + bv.w + xv.w;
    }

    // LayerNorm over 96 channels (warp reduce, lanes>=24 contribute 0)
    float v1 = (lane < 24) ? (o.x + o.y) + (o.z + o.w) : 0.f;
    float v2 = (lane < 24) ? (o.x * o.x + o.y * o.y) + (o.z * o.z + o.w * o.w) : 0.f;
#pragma unroll
    for (int off = 16; off > 0; off >>= 1) {
        v1 += __shfl_down_sync(0xffffffffu, v1, off);
        v2 += __shfl_down_sync(0xffffffffu, v2, off);
    }
    float mu  = __shfl_sync(0xffffffffu, v1, 0) * (1.f / 96.f);
    float msq = __shfl_sync(0xffffffffu, v2, 0) * (1.f / 96.f);
    float inv = rsqrtf(msq - mu * mu + LN_EPS);

    if (lane < 24) {
        float4 gv = __ldg((const float4*)&gamma[lane * 4]);
        float4 btv = __ldg((const float4*)&beta[lane * 4]);
        float4 y;
        y.x = fmaxf((o.x - mu) * inv * gv.x + btv.x, 0.f);
        y.y = fmaxf((o.y - mu) * inv * gv.y + btv.y, 0.f);
        y.z = fmaxf((o.z - mu) * inv * gv.z + btv.z, 0.f);
        y.w = fmaxf((o.w - mu) * inv * gv.w + btv.w, 0.f);
        ((float4*)out)[i * 24 + lane] = y;
    }
}

// ---------------- launch ----------------
extern "C" void kernel_launch(void* const* d_in, const int* in_sizes, int n_in,
                              void* d_out, int out_size) {
    const float* x        = (const float*)d_in[0];
    const int*   ei       = (const int*)d_in[1];
    const float* W        = (const float*)d_in[2];
    const float* att_src  = (const float*)d_in[3];
    const float* att_dst  = (const float*)d_in[4];
    const float* bias     = (const float*)d_in[5];
    const float* gamma    = (const float*)d_in[6];
    const float* beta     = (const float*)d_in[7];
    float* out = (float*)d_out;

    int n = in_sizes[0] / C;       // 50000
    int e = in_sizes[1] / 2;       // 800000
    int e4 = e >> 2;

    int gemm_blocks = (n + GR - 1) / GR;          // 782
    int GB1 = (gemm_blocks + 1) / 2;
    int GB2 = gemm_blocks - GB1;
    int csr_blocks = (e4 + GEMM_THREADS) / GEMM_THREADS;

    kzero<<<(n + 255) / 256, 256>>>(n);
    kfused1<<<GB1 + csr_blocks, GEMM_THREADS>>>(x, W, att_src, att_dst, n, GB1, ei + e, e);
    kscan<<<NBLK_SCAN, 256>>>(n);
    kfused2<<<GB2 + csr_blocks, GEMM_THREADS>>>(x, W, att_src, att_dst, n, GB1, GB2, ei, e);
    kmain<<<(n + 7) / 8, 256>>>(x, bias, gamma, beta, out, n);
}